// round 2
// baseline (speedup 1.0000x reference)
#include <cuda_runtime.h>
#include <cuda_fp16.h>
#include <stdint.h>

#define BB    128          // batch
#define TT    512          // seq len
#define HH    256          // hidden
#define LL    6            // layers
#define INW   128          // input width (layer 0)
#define FOURH 1024         // 4*H
#define NC    16           // CTAs per layer
#define GRIDB (LL*NC)      // 96
#define NTH   256
#define KMAX  512
#define SMEM_BYTES (192*(2*HH+8)*2)   // (64 w-rows + 128 act-rows) * (520 halfs) * 2B = 199680

// ---------------- persistent device state (static allocation only) ----------
__device__ __align__(256) __half d_wpack[(size_t)LL*FOURH*KMAX];  // fp16 [Wih|Whh], gate-packed rows
__device__ __align__(256) float  d_bpack[LL*FOURH];               // b_ih + b_hh, packed order
__device__ __align__(256) __half d_xh[(size_t)BB*TT*INW];         // x in fp16
__device__ __align__(256) __half d_hring[LL*4*BB*HH];             // 4-slot h ring per layer
__device__ unsigned g_arrive[LL];                                 // monotonic per-layer progress

__device__ __forceinline__ int hring_off(int l, int slot, int b, int k){
  return ((l*4 + slot)*BB + b)*HH + k;
}

// ---------------- prep kernels (run every call: deterministic, graph-safe) --
__global__ void prep_pack(const float* __restrict__ w_ih0,
                          const float* __restrict__ w_ih,
                          const float* __restrict__ w_hh,
                          const float* __restrict__ b_ih,
                          const float* __restrict__ b_hh){
  long long idx = (long long)blockIdx.x*blockDim.x + threadIdx.x;
  if (idx >= (long long)LL*FOURH*KMAX) return;
  int k = (int)(idx % KMAX);
  int p = (int)((idx / KMAX) % FOURH);
  int l = (int)(idx / ((long long)KMAX*FOURH));
  int cid = p >> 6, rr = p & 63, gate = rr >> 4, jj = rr & 15;
  int srow = gate*HH + cid*16 + jj;       // original 4H row (PyTorch i,f,g,o order)
  int din  = (l == 0) ? INW : HH;
  float v = 0.f;
  if (k < din)            v = (l == 0) ? w_ih0[srow*INW + k]
                                       : w_ih[((size_t)(l-1)*FOURH + srow)*HH + k];
  else if (k < din + HH)  v = w_hh[((size_t)l*FOURH + srow)*HH + (k - din)];
  d_wpack[idx] = __float2half(v);
  if (k == 0) d_bpack[l*FOURH + p] = b_ih[l*FOURH + srow] + b_hh[l*FOURH + srow];
}

__global__ void prep_x(const float* __restrict__ x){
  long long i = (long long)blockIdx.x*blockDim.x + threadIdx.x;
  if (i < (long long)BB*TT*INW) d_xh[i] = __float2half(x[i]);
}

__global__ void prep_init(const float* __restrict__ h0){
  int i = blockIdx.x*blockDim.x + threadIdx.x;
  if (i < LL*BB*HH){
    int l = i/(BB*HH), rem = i%(BB*HH);
    d_hring[hring_off(l, 0, rem/HH, rem%HH)] = __float2half(h0[i]);
  }
  if (i == 0){
    #pragma unroll
    for (int l = 0; l < LL; l++) g_arrive[l] = 0u;
  }
}

// ---------------- low-level helpers ----------------
__device__ __forceinline__ unsigned smem_u32(const void* p){
  return (unsigned)__cvta_generic_to_shared(p);
}
__device__ __forceinline__ void ldsm_x4(unsigned addr, unsigned& r0, unsigned& r1,
                                        unsigned& r2, unsigned& r3){
  asm volatile("ldmatrix.sync.aligned.m8n8.x4.shared.b16 {%0,%1,%2,%3}, [%4];\n"
               : "=r"(r0), "=r"(r1), "=r"(r2), "=r"(r3) : "r"(addr));
}
__device__ __forceinline__ void mma_16816(float d[4], const unsigned a[4], const unsigned b0,
                                          const unsigned b1){
  asm volatile("mma.sync.aligned.m16n8k16.row.col.f32.f16.f16.f32 "
               "{%0,%1,%2,%3}, {%4,%5,%6,%7}, {%8,%9}, {%0,%1,%2,%3};\n"
               : "+f"(d[0]), "+f"(d[1]), "+f"(d[2]), "+f"(d[3])
               : "r"(a[0]), "r"(a[1]), "r"(a[2]), "r"(a[3]), "r"(b0), "r"(b1));
}
__device__ __forceinline__ float sigmoidf_(float x){ return 1.f/(1.f + __expf(-x)); }
__device__ __forceinline__ float tanhf_(float x){
  float e = __expf(-2.f*fabsf(x));
  return copysignf((1.f - e)/(1.f + e), x);
}
__device__ __forceinline__ void wait_ge(unsigned* p, unsigned target){
  unsigned v;
  #pragma unroll 1
  while (true){
    asm volatile("ld.acquire.gpu.global.u32 %0, [%1];" : "=r"(v) : "l"(p) : "memory");
    if (v >= target) break;
    __nanosleep(64);
  }
}
__device__ __forceinline__ void arrive_release(unsigned* p){
  asm volatile("red.release.gpu.global.add.u32 [%0], %1;" :: "l"(p), "r"(1u) : "memory");
}

// ---------------- per-layer persistent worker ----------------
template<int KL, int DINA>
__device__ __forceinline__ void run_layer(const int l, const int cid,
                                          const float* __restrict__ c0,
                                          float* __restrict__ out, char* smem_raw)
{
  constexpr int SI = KL + 8;                 // padded row stride in halfs (16B shift / 8 rows)
  __half* ws  = (__half*)smem_raw;           // [64][SI]  weights (persistent)
  __half* inp = ws + 64*SI;                  // [128][SI] activations (aliased by gsh)
  float*  gsh = (float*)inp;                 // [128][65] gate accumulators
  const int tid = threadIdx.x;

  // ---- load this CTA's 64 packed weight rows into smem (once) ----
  {
    const __half* src = d_wpack + ((size_t)(l*FOURH + cid*64))*KMAX;
    constexpr int vec = KL/8;
    for (int v = tid; v < 64*vec; v += NTH){
      int r = v / vec, kk = (v - r*vec)*8;
      *(uint4*)(ws + r*SI + kk) = *(const uint4*)(src + (size_t)r*KMAX + kk);
    }
  }

  // ---- per-thread gate ownership: (jj, m0): column col, 8 batch rows ----
  const int jj = tid & 15, m0 = tid >> 4;
  const int col = cid*16 + jj;
  const float bI = d_bpack[l*FOURH + cid*64 +      jj];
  const float bF = d_bpack[l*FOURH + cid*64 + 16 + jj];
  const float bG = d_bpack[l*FOURH + cid*64 + 32 + jj];
  const float bO = d_bpack[l*FOURH + cid*64 + 48 + jj];

  float creg[8];                             // cell state: registers for all 512 steps
  #pragma unroll
  for (int i = 0; i < 8; i++)
    creg[i] = c0[(l*BB + m0 + 16*i)*HH + col];

  // ---- mma thread mapping: 8 warps = M4 x N2 ----
  const int w = tid >> 5, lane = tid & 31;
  const int wm = w & 3, wn = w >> 2;
  const int q = lane >> 3, rs = lane & 7;
  const int gid = lane >> 2, ct = lane & 3;

  const unsigned aBase0 = smem_u32(inp + (wm*32 + rs + ((q&1)<<3))*SI + ((q>>1)<<3));
  const unsigned aBase1 = aBase0 + (unsigned)(32*SI);   // +16 rows (bytes)
  const unsigned bBase0 = smem_u32(ws  + (wn*32 + rs + ((q>>1)<<3))*SI + ((q&1)<<3));
  const unsigned bBase1 = bBase0 + (unsigned)(32*SI);   // +16 weight rows

  for (int t = 0; t < TT; t++){
    // ---- dependency waits (monotonic counters; acquire semantics) ----
    if (tid == 0){
      if (t > 0)               wait_ge(&g_arrive[l],   16u*(unsigned)t);        // peers done t-1
      if (l > 0)               wait_ge(&g_arrive[l-1], 16u*(unsigned)(t+1));    // below done t
      if (l < LL-1 && t >= 3)  wait_ge(&g_arrive[l+1], 16u*(unsigned)(t-2));    // ring WAR safe
    }
    __syncthreads();

    // ---- stage input tile [128][KL] = [below | own h_{t-1}] into smem ----
    if (DINA == INW){                                   // layer 0: x (L1-cacheable)
      for (int v = tid; v < BB*(INW/8); v += NTH){
        int b = v >> 4, kk = (v & 15)*8;
        *(uint4*)(inp + b*SI + kk) = *(const uint4*)(d_xh + ((size_t)b*TT + t)*INW + kk);
      }
    } else {                                            // h from layer below: L2-coherent
      const __half* srcA = d_hring + hring_off(l-1, (t+1)&3, 0, 0);
      for (int v = tid; v < BB*(HH/8); v += NTH){
        int b = v >> 5, kk = (v & 31)*8;
        *(uint4*)(inp + b*SI + kk) = __ldcg((const uint4*)(srcA + b*HH + kk));
      }
    }
    {
      const __half* srcB = d_hring + hring_off(l, t&3, 0, 0);
      for (int v = tid; v < BB*(HH/8); v += NTH){
        int b = v >> 5, kk = (v & 31)*8;
        *(uint4*)(inp + b*SI + DINA + kk) = __ldcg((const uint4*)(srcB + b*HH + kk));
      }
    }
    __syncthreads();

    // ---- GEMM: g[128][64] = inp[128][KL] * W[64][KL]^T ----
    float acc[2][4][4];
    #pragma unroll
    for (int i = 0; i < 2; i++)
      #pragma unroll
      for (int j = 0; j < 4; j++)
        #pragma unroll
        for (int kx = 0; kx < 4; kx++) acc[i][j][kx] = 0.f;

    #pragma unroll
    for (int k0 = 0; k0 < KL; k0 += 16){
      unsigned a0[4], a1[4], bf0[2], bf1[2], bf2[2], bf3[2];
      ldsm_x4(aBase0 + (unsigned)(k0*2), a0[0], a0[1], a0[2], a0[3]);
      ldsm_x4(aBase1 + (unsigned)(k0*2), a1[0], a1[1], a1[2], a1[3]);
      ldsm_x4(bBase0 + (unsigned)(k0*2), bf0[0], bf0[1], bf1[0], bf1[1]);
      ldsm_x4(bBase1 + (unsigned)(k0*2), bf2[0], bf2[1], bf3[0], bf3[1]);
      mma_16816(acc[0][0], a0, bf0[0], bf0[1]);
      mma_16816(acc[1][0], a1, bf0[0], bf0[1]);
      mma_16816(acc[0][1], a0, bf1[0], bf1[1]);
      mma_16816(acc[1][1], a1, bf1[0], bf1[1]);
      mma_16816(acc[0][2], a0, bf2[0], bf2[1]);
      mma_16816(acc[1][2], a1, bf2[0], bf2[1]);
      mma_16816(acc[0][3], a0, bf3[0], bf3[1]);
      mma_16816(acc[1][3], a1, bf3[0], bf3[1]);
    }
    __syncthreads();                 // all ldmatrix reads of inp done; gsh aliases it

    // ---- spill g tile (fp32) to smem for gate re-partitioning ----
    #pragma unroll
    for (int mt = 0; mt < 2; mt++)
      #pragma unroll
      for (int nt = 0; nt < 4; nt++){
        int row  = wm*32 + mt*16 + gid;
        int colc = wn*32 + nt*8 + ct*2;
        gsh[ row   *65 + colc    ] = acc[mt][nt][0];
        gsh[ row   *65 + colc + 1] = acc[mt][nt][1];
        gsh[(row+8)*65 + colc    ] = acc[mt][nt][2];
        gsh[(row+8)*65 + colc + 1] = acc[mt][nt][3];
      }
    __syncthreads();

    // ---- gates; c stays in registers; h -> L2 ring (stcg) ----
    {
      __half* hdst = d_hring + hring_off(l, (t+1)&3, 0, col);
      #pragma unroll
      for (int i = 0; i < 8; i++){
        int m = m0 + 16*i;
        float gi = gsh[m*65 +      jj] + bI;
        float gf = gsh[m*65 + 16 + jj] + bF;
        float gg = gsh[m*65 + 32 + jj] + bG;
        float go = gsh[m*65 + 48 + jj] + bO;
        float c  = sigmoidf_(gf)*creg[i] + sigmoidf_(gi)*tanhf_(gg);
        creg[i]  = c;
        float hv = sigmoidf_(go)*tanhf_(c);
        __stcg((unsigned short*)(hdst + m*HH), (unsigned short)__half_as_ushort(__float2half(hv)));
        if (t == TT-1) out[(l*BB + m)*HH + col] = hv;
      }
    }
    __threadfence();                 // each thread: h stores visible at gpu scope
    __syncthreads();
    if (tid == 0) arrive_release(&g_arrive[l]);
  }
}

__global__ void __launch_bounds__(NTH, 1)
lstm_persist(const float* __restrict__ c0, float* __restrict__ out)
{
  extern __shared__ __align__(16) char smem_raw[];
  const int l = blockIdx.x >> 4, cid = blockIdx.x & 15;
  if (l == 0) run_layer<INW + HH, INW>(0, cid, c0, out, smem_raw);
  else        run_layer<2*HH,    HH >(l, cid, c0, out, smem_raw);
}

// ---------------- launch ----------------
extern "C" void kernel_launch(void* const* d_in, const int* in_sizes, int n_in,
                              void* d_out, int out_size){
  const float* x     = (const float*)d_in[0];
  const float* h0    = (const float*)d_in[1];
  const float* c0    = (const float*)d_in[2];
  const float* w_ih0 = (const float*)d_in[3];
  const float* w_ih  = (const float*)d_in[4];
  const float* w_hh  = (const float*)d_in[5];
  const float* b_ih  = (const float*)d_in[6];
  const float* b_hh  = (const float*)d_in[7];
  float* out = (float*)d_out;

  cudaFuncSetAttribute(lstm_persist, cudaFuncAttributeMaxDynamicSharedMemorySize, SMEM_BYTES);

  prep_pack<<<(LL*FOURH*KMAX + 255)/256, 256>>>(w_ih0, w_ih, w_hh, b_ih, b_hh);
  prep_x   <<<(BB*TT*INW    + 255)/256, 256>>>(x);
  prep_init<<<(LL*BB*HH     + 255)/256, 256>>>(h0);
  lstm_persist<<<GRIDB, NTH, SMEM_BYTES>>>(c0, out);
}

// round 3
// speedup vs baseline: 1.3994x; 1.3994x over previous
#include <cuda_runtime.h>
#include <cuda_fp16.h>
#include <stdint.h>

#define BB    128          // batch
#define TT    512          // seq len
#define HH    256          // hidden
#define LL    6            // layers
#define INW   128          // input width (layer 0)
#define FOURH 1024         // 4*H
#define NC    16           // CTAs per layer
#define GRIDB (LL*NC)      // 96
#define NTH   256
#define KMAX  512
#define SMEM_BYTES (192*(2*HH+8)*2)   // (64 w-rows + 128 act-rows) * 520 halfs * 2B = 199680

// ---------------- persistent device state (static allocation only) ----------
__device__ __align__(256) __half d_wpack[(size_t)LL*FOURH*KMAX];  // fp16 [Wih|Whh], gate-packed rows
__device__ __align__(256) float  d_bpack[LL*FOURH];               // b_ih + b_hh, packed order
__device__ __align__(256) __half d_xh[(size_t)BB*TT*INW];         // x in fp16
__device__ __align__(256) __half d_hring[LL*4*BB*HH];             // 4-slot h ring per layer
__device__ unsigned g_arrive[LL];                                 // monotonic per-layer progress

__device__ __forceinline__ int hring_off(int l, int slot, int b, int k){
  return ((l*4 + slot)*BB + b)*HH + k;
}

// ---------------- prep kernels (run every call: deterministic, graph-safe) --
__global__ void prep_pack(const float* __restrict__ w_ih0,
                          const float* __restrict__ w_ih,
                          const float* __restrict__ w_hh,
                          const float* __restrict__ b_ih,
                          const float* __restrict__ b_hh){
  long long idx = (long long)blockIdx.x*blockDim.x + threadIdx.x;
  if (idx >= (long long)LL*FOURH*KMAX) return;
  int k = (int)(idx % KMAX);
  int p = (int)((idx / KMAX) % FOURH);
  int l = (int)(idx / ((long long)KMAX*FOURH));
  int cid = p >> 6, rr = p & 63, gate = rr >> 4, jj = rr & 15;
  int srow = gate*HH + cid*16 + jj;       // original 4H row (PyTorch i,f,g,o order)
  int din  = (l == 0) ? INW : HH;
  float v = 0.f;
  if (k < din)            v = (l == 0) ? w_ih0[srow*INW + k]
                                       : w_ih[((size_t)(l-1)*FOURH + srow)*HH + k];
  else if (k < din + HH)  v = w_hh[((size_t)l*FOURH + srow)*HH + (k - din)];
  d_wpack[idx] = __float2half(v);
  if (k == 0) d_bpack[l*FOURH + p] = b_ih[l*FOURH + srow] + b_hh[l*FOURH + srow];
}

__global__ void prep_x(const float* __restrict__ x){
  long long i = (long long)blockIdx.x*blockDim.x + threadIdx.x;
  if (i < (long long)BB*TT*INW) d_xh[i] = __float2half(x[i]);
}

__global__ void prep_init(const float* __restrict__ h0){
  int i = blockIdx.x*blockDim.x + threadIdx.x;
  if (i < LL*BB*HH){
    int l = i/(BB*HH), rem = i%(BB*HH);
    d_hring[hring_off(l, 0, rem/HH, rem%HH)] = __float2half(h0[i]);
  }
  if (i == 0){
    #pragma unroll
    for (int l = 0; l < LL; l++) g_arrive[l] = 0u;
  }
}

// ---------------- low-level helpers ----------------
__device__ __forceinline__ unsigned smem_u32(const void* p){
  return (unsigned)__cvta_generic_to_shared(p);
}
__device__ __forceinline__ void ldsm_x4(unsigned addr, unsigned& r0, unsigned& r1,
                                        unsigned& r2, unsigned& r3){
  asm volatile("ldmatrix.sync.aligned.m8n8.x4.shared.b16 {%0,%1,%2,%3}, [%4];\n"
               : "=r"(r0), "=r"(r1), "=r"(r2), "=r"(r3) : "r"(addr));
}
__device__ __forceinline__ void mma_16816(float d[4], const unsigned a[4], const unsigned b0,
                                          const unsigned b1){
  asm volatile("mma.sync.aligned.m16n8k16.row.col.f32.f16.f16.f32 "
               "{%0,%1,%2,%3}, {%4,%5,%6,%7}, {%8,%9}, {%0,%1,%2,%3};\n"
               : "+f"(d[0]), "+f"(d[1]), "+f"(d[2]), "+f"(d[3])
               : "r"(a[0]), "r"(a[1]), "r"(a[2]), "r"(a[3]), "r"(b0), "r"(b1));
}
__device__ __forceinline__ float tanh_fast(float x){
  float r; asm("tanh.approx.f32 %0, %1;" : "=f"(r) : "f"(x)); return r;
}
__device__ __forceinline__ float sig_fast(float x){
  return fmaf(tanh_fast(0.5f*x), 0.5f, 0.5f);
}
__device__ __forceinline__ void wait_ge(unsigned* p, unsigned target){
  unsigned v;
  #pragma unroll 1
  do {
    asm volatile("ld.acquire.gpu.global.u32 %0, [%1];" : "=r"(v) : "l"(p) : "memory");
  } while (v < target);
}
__device__ __forceinline__ void arrive_release(unsigned* p){
  asm volatile("red.release.gpu.global.add.u32 [%0], %1;" :: "l"(p), "r"(1u) : "memory");
}
__device__ __forceinline__ void st_cg_u32(void* p, unsigned v){
  asm volatile("st.global.cg.u32 [%0], %1;" :: "l"(p), "r"(v) : "memory");
}

// ---------------- per-layer persistent worker ----------------
// Warp layout: 8 warps = M4 x N2. Warp (wm, wn) computes rows [wm*32, wm*32+32)
// of all FOUR gate groups for h-columns j in [wn*8, wn*8+8). Gate rows in the
// packed 64-row weight chunk: gate*16 + j. So each warp's B tiles are the four
// 8-row groups {g*16 + wn*8 .. +8}, g=0..3 -> all gates of a column live in ONE
// warp's accumulators => gate math entirely in registers (no smem round-trip).
template<int KL, int DINA>
__device__ __forceinline__ void run_layer(const int l, const int cid,
                                          const float* __restrict__ c0,
                                          float* __restrict__ out, char* smem_raw)
{
  constexpr int SI = KL + 8;                 // padded row stride in halfs (16B shift / row)
  __half* ws  = (__half*)smem_raw;           // [64][SI]  weights (persistent)
  __half* inp = ws + 64*SI;                  // [128][SI] activations
  const int tid = threadIdx.x;

  // ---- load this CTA's 64 packed weight rows into smem (once) ----
  {
    const __half* src = d_wpack + ((size_t)(l*FOURH + cid*64))*KMAX;
    constexpr int vec = KL/8;
    for (int v = tid; v < 64*vec; v += NTH){
      int r = v / vec, kk = (v - r*vec)*8;
      *(uint4*)(ws + r*SI + kk) = *(const uint4*)(src + (size_t)r*KMAX + kk);
    }
  }

  // ---- thread mapping ----
  const int w = tid >> 5, lane = tid & 31;
  const int wm = w & 3, wn = w >> 2;
  const int q = lane >> 3, rs = lane & 7;
  const int gid = lane >> 2, ct = lane & 3;

  // A: m16k16 tiles, rows wm*32 + {0..15} (+16 for second M tile)
  const unsigned aBase0 = smem_u32(inp + (wm*32 + rs + ((q&1)<<3))*SI + ((q>>1)<<3));
  const unsigned aBase1 = aBase0 + (unsigned)(32*SI);            // +16 rows (bytes)
  // B: per ldsm.x4 -> two gate groups' n8k16 frags: rows g*16 + wn*8 + {0..7}
  const unsigned bBase0 = smem_u32(ws + (wn*8 + rs + ((q>>1)<<4))*SI + ((q&1)<<3)); // gates 0,1
  const unsigned bBase1 = bBase0 + (unsigned)(64*SI);            // +32 rows: gates 2,3

  // ---- per-thread gate cell ownership: rows r(mt,rr), cols j(cc) ----
  // r = wm*32 + mt*16 + gid + rr*8 ; j = wn*8 + ct*2 + cc ; colglob = cid*16 + j
  float bias[4][2];
  #pragma unroll
  for (int g = 0; g < 4; g++)
    #pragma unroll
    for (int cc = 0; cc < 2; cc++)
      bias[g][cc] = d_bpack[l*FOURH + cid*64 + g*16 + wn*8 + ct*2 + cc];

  float creg[8];                             // cell state: registers for all 512 steps
  #pragma unroll
  for (int mt = 0; mt < 2; mt++)
    #pragma unroll
    for (int rr = 0; rr < 2; rr++)
      #pragma unroll
      for (int cc = 0; cc < 2; cc++){
        int r = wm*32 + mt*16 + gid + rr*8;
        int cg = cid*16 + wn*8 + ct*2 + cc;
        creg[mt*4 + rr*2 + cc] = c0[(l*BB + r)*HH + cg];
      }

  for (int t = 0; t < TT; t++){
    // ---- dependency waits (monotonic counters; acquire) ----
    if (tid == 0){
      if (l > 0)               wait_ge(&g_arrive[l-1], 16u*(unsigned)(t+1));    // below done t
      if (t > 0)               wait_ge(&g_arrive[l],   16u*(unsigned)t);        // peers done t-1
      if (l < LL-1 && t >= 3)  wait_ge(&g_arrive[l+1], 16u*(unsigned)(t-2));    // ring WAR safe
    }
    __syncthreads();

    // ---- stage input tile [128][KL] = [below | own h_{t-1}] into smem ----
    if (DINA == INW){                                   // layer 0: x (L1-cacheable)
      for (int v = tid; v < BB*(INW/8); v += NTH){
        int b = v >> 4, kk = (v & 15)*8;
        *(uint4*)(inp + b*SI + kk) = *(const uint4*)(d_xh + ((size_t)b*TT + t)*INW + kk);
      }
    } else {                                            // h from layer below: L2-coherent
      const __half* srcA = d_hring + hring_off(l-1, (t+1)&3, 0, 0);
      for (int v = tid; v < BB*(HH/8); v += NTH){
        int b = v >> 5, kk = (v & 31)*8;
        *(uint4*)(inp + b*SI + kk) = __ldcg((const uint4*)(srcA + b*HH + kk));
      }
    }
    {
      const __half* srcB = d_hring + hring_off(l, t&3, 0, 0);
      for (int v = tid; v < BB*(HH/8); v += NTH){
        int b = v >> 5, kk = (v & 31)*8;
        *(uint4*)(inp + b*SI + DINA + kk) = __ldcg((const uint4*)(srcB + b*HH + kk));
      }
    }
    __syncthreads();

    // ---- GEMM: acc[mt][gate][4] ; rows wm*32+mt*16+.., gate groups, cols wn*8+.. ----
    float acc[2][4][4];
    #pragma unroll
    for (int i = 0; i < 2; i++)
      #pragma unroll
      for (int j = 0; j < 4; j++)
        #pragma unroll
        for (int kx = 0; kx < 4; kx++) acc[i][j][kx] = 0.f;

    #pragma unroll 8
    for (int k0 = 0; k0 < KL; k0 += 16){
      unsigned a0[4], a1[4], b01[4], b23[4];
      ldsm_x4(aBase0 + (unsigned)(k0*2), a0[0], a0[1], a0[2], a0[3]);
      ldsm_x4(aBase1 + (unsigned)(k0*2), a1[0], a1[1], a1[2], a1[3]);
      ldsm_x4(bBase0 + (unsigned)(k0*2), b01[0], b01[1], b01[2], b01[3]);
      ldsm_x4(bBase1 + (unsigned)(k0*2), b23[0], b23[1], b23[2], b23[3]);
      mma_16816(acc[0][0], a0, b01[0], b01[1]);   // gate i
      mma_16816(acc[1][0], a1, b01[0], b01[1]);
      mma_16816(acc[0][1], a0, b01[2], b01[3]);   // gate f
      mma_16816(acc[1][1], a1, b01[2], b01[3]);
      mma_16816(acc[0][2], a0, b23[0], b23[1]);   // gate g
      mma_16816(acc[1][2], a1, b23[0], b23[1]);
      mma_16816(acc[0][3], a0, b23[2], b23[3]);   // gate o
      mma_16816(acc[1][3], a1, b23[2], b23[3]);
    }

    // ---- gates in registers; c stays in registers; h -> L2 ring ----
    {
      __half* hslot = d_hring + hring_off(l, (t+1)&3, 0, 0);
      #pragma unroll
      for (int mt = 0; mt < 2; mt++)
        #pragma unroll
        for (int rr = 0; rr < 2; rr++){
          int r  = wm*32 + mt*16 + gid + rr*8;
          float hv[2];
          #pragma unroll
          for (int cc = 0; cc < 2; cc++){
            int e  = rr*2 + cc;
            int ci = mt*4 + rr*2 + cc;
            float gi = acc[mt][0][e] + bias[0][cc];
            float gf = acc[mt][1][e] + bias[1][cc];
            float gg = acc[mt][2][e] + bias[2][cc];
            float go = acc[mt][3][e] + bias[3][cc];
            float c  = sig_fast(gf)*creg[ci] + sig_fast(gi)*tanh_fast(gg);
            creg[ci] = c;
            hv[cc]   = sig_fast(go)*tanh_fast(c);
          }
          int cg0 = cid*16 + wn*8 + ct*2;
          __half2 h2 = __floats2half2_rn(hv[0], hv[1]);
          st_cg_u32(hslot + r*HH + cg0, *(unsigned*)&h2);
          if (t == TT-1){
            out[(l*BB + r)*HH + cg0    ] = hv[0];
            out[(l*BB + r)*HH + cg0 + 1] = hv[1];
          }
        }
    }
    __syncthreads();                 // all ldsm reads of inp done + all h stores issued
    if (tid == 0) arrive_release(&g_arrive[l]);
  }
}

__global__ void __launch_bounds__(NTH, 1)
lstm_persist(const float* __restrict__ c0, float* __restrict__ out)
{
  extern __shared__ __align__(16) char smem_raw[];
  const int l = blockIdx.x >> 4, cid = blockIdx.x & 15;
  if (l == 0) run_layer<INW + HH, INW>(0, cid, c0, out, smem_raw);
  else        run_layer<2*HH,    HH >(l, cid, c0, out, smem_raw);
}

// ---------------- launch ----------------
extern "C" void kernel_launch(void* const* d_in, const int* in_sizes, int n_in,
                              void* d_out, int out_size){
  const float* x     = (const float*)d_in[0];
  const float* h0    = (const float*)d_in[1];
  const float* c0    = (const float*)d_in[2];
  const float* w_ih0 = (const float*)d_in[3];
  const float* w_ih  = (const float*)d_in[4];
  const float* w_hh  = (const float*)d_in[5];
  const float* b_ih  = (const float*)d_in[6];
  const float* b_hh  = (const float*)d_in[7];
  float* out = (float*)d_out;

  cudaFuncSetAttribute(lstm_persist, cudaFuncAttributeMaxDynamicSharedMemorySize, SMEM_BYTES);

  prep_pack<<<(LL*FOURH*KMAX + 255)/256, 256>>>(w_ih0, w_ih, w_hh, b_ih, b_hh);
  prep_x   <<<(BB*TT*INW    + 255)/256, 256>>>(x);
  prep_init<<<(LL*BB*HH     + 255)/256, 256>>>(h0);
  lstm_persist<<<GRIDB, NTH, SMEM_BYTES>>>(c0, out);
}